// round 15
// baseline (speedup 1.0000x reference)
#include <cuda_runtime.h>
#include <cuda_fp16.h>
#include <mma.h>
#include <math.h>
#include <stdint.h>
#include <cstdint>

using namespace nvcuda;

#define AS 136    // fp16 tile stride (halfs, mult of 8)
#define FS 136    // f32 scratch stride (floats)
#define HS2 136   // half scratch stride (halfs)
#define SHS 72    // fp16 score row stride (halfs, mult of 8)
#define HB (64*SHS)  // per-head S block (halfs)
#define RFS 132   // residual f32 row stride (floats, mult of 4)

// fp16 pre-converted weights (written by cvt_weights_kernel each launch)
// Q columns of qkv_w are pre-scaled by 1/sqrt(HD).
__device__ __align__(16) __half g_qkvwh[128*384];
__device__ __align__(16) __half g_projwh[128*128];
__device__ __align__(16) __half g_w1h[128*512];
__device__ __align__(16) __half g_w2h[512*128];

// ---------------------------------------------------------------------------
__global__ void cvt_weights_kernel(const float* __restrict__ qkv_w,
                                   const float* __restrict__ proj_w,
                                   const float* __restrict__ w1,
                                   const float* __restrict__ w2)
{
    const int i4 = (blockIdx.x*256 + threadIdx.x) * 4;   // grid 192 -> 196608
    const float* src; __half* dst; int off;
    float scale = 1.f;
    if (i4 < 49152) {
        src = qkv_w;  dst = g_qkvwh;  off = i4;
        if ((off % 384) < 128) scale = 0.17677669529663687f;   // fold qscale into Q
    }
    else if (i4 < 65536)  { src = proj_w; dst = g_projwh; off = i4 - 49152; }
    else if (i4 < 131072) { src = w1;     dst = g_w1h;    off = i4 - 65536; }
    else                  { src = w2;     dst = g_w2h;    off = i4 - 131072; }
    const float4 v = *(const float4*)(src + off);
    dst[off+0] = __float2half(v.x*scale); dst[off+1] = __float2half(v.y*scale);
    dst[off+2] = __float2half(v.z*scale); dst[off+3] = __float2half(v.w*scale);
}

// ---------------------------------------------------------------------------
// Fused 2-window kernel: each CTA (512 thr) processes TWO windows sharing one
// staged weight buffer. Per window: LN1 -> QKV -> attention -> proj ->
// residual(smem) -> LN2 -> MLP -> scatter. grid 2048, 1 CTA/SM.
// SMEM: [win0 tiles 4x17408][win1 tiles 4x17408][U 73728][bias][lab][orow]
// ---------------------------------------------------------------------------
__global__ void __launch_bounds__(512, 1) swin_block_kernel(
    const float* __restrict__ inp,
    const float* __restrict__ proj_b,
    const float* __restrict__ bias_table,
    const float* __restrict__ g1,
    const float* __restrict__ b1,
    const float* __restrict__ g2,
    const float* __restrict__ b2,
    const float* __restrict__ bb1,
    const float* __restrict__ bb2,
    float* __restrict__ out)
{
    extern __shared__ char sma[];
    const int tid  = threadIdx.x;
    const int win  = tid >> 8;            // window within CTA (0/1)
    const int t256 = tid & 255;           // thread within window
    const int wid  = tid >> 5;            // warp 0..15
    const int w8   = wid & 7;             // warp within window
    const int lane = tid & 31;

    __half* Xh = (__half*)sma + win*(4*64*AS);  // LN'd X; O; MLP A1
    __half* Qh = Xh + 64*AS;                    // Q; MLP A2
    __half* Kh = Qh + 64*AS;                    // K; later Rf
    __half* Vh = Kh + 64*AS;                    // V
    char*   U  = sma + 2*(4*64*AS)*2;           // 73728B union
    __half* Wc  = (__half*)U;                   // shared weights (34816B)
    __half* Sh  = (__half*)(U + win*36864);     // per-window scores
    __half* Ph2 = (__half*)(U + win*17408);     // per-window proj scratch
    __half* Hs  = (__half*)(U + win*17408);     // per-window gemm1 scratch
    float*  Ff  = (float*)(U + win*34816);      // per-window f32 scratch
    float*  Rf  = (float*)Kh;                   // per-window residual (33792B)
    float*  bias_s  = (float*)(U + 73728);      // 484 (shared)
    int*    lab_all = (int*)(bias_s + 484);     // 128
    int*    lab_s   = lab_all + win*64;
    int*    orow_s  = lab_all + 128 + win*64;

    const int wblk = blockIdx.x*2 + win;
    const int bb = wblk >> 9;
    const int wi = wblk & 511;
    const int gx = wi >> 6, gy = (wi >> 3) & 7, gz = wi & 7;

    for (int i = tid; i < 484; i += 512) bias_s[i] = bias_table[i];

    if (t256 < 64) {
        const int lx = t256 >> 4, ly = (t256 >> 2) & 3, lz = t256 & 3;
        const int px = gx*4 + lx, py = gy*4 + ly, pz = gz*4 + lz;
        const int ox = (px + 2) & 31, oy = (py + 2) & 31, oz = (pz + 2) & 31;
        orow_s[t256] = ((bb*32 + ox)*32 + oy)*32 + oz;
        const int labx = px < 28 ? 0 : (px < 30 ? 1 : 2);
        const int laby = py < 28 ? 0 : (py < 30 ? 1 : 2);
        const int labz = pz < 28 ? 0 : (pz < 30 ? 1 : 2);
        lab_s[t256] = labx*9 + laby*3 + labz;
    }
    __syncthreads();

    // ---- Phase 1: LayerNorm -> fp16 Xh ----
    {
        const float4 gv = *(const float4*)(g1 + lane*4);
        const float4 bv = *(const float4*)(b1 + lane*4);
        for (int t = w8*8; t < w8*8 + 8; ++t) {
            const float* row = inp + (long)orow_s[t]*128;
            const float4 x4 = *(const float4*)(row + lane*4);
            float s = x4.x + x4.y + x4.z + x4.w;
            float q = x4.x*x4.x + x4.y*x4.y + x4.z*x4.z + x4.w*x4.w;
            #pragma unroll
            for (int o = 16; o; o >>= 1) {
                s += __shfl_xor_sync(0xffffffffu, s, o);
                q += __shfl_xor_sync(0xffffffffu, q, o);
            }
            const float m = s * 0.0078125f;
            const float rstd = rsqrtf(q*0.0078125f - m*m + 1e-5f);
            __half* dst = Xh + t*AS + lane*4;
            dst[0] = __float2half((x4.x - m)*rstd*gv.x + bv.x);
            dst[1] = __float2half((x4.y - m)*rstd*gv.y + bv.y);
            dst[2] = __float2half((x4.z - m)*rstd*gv.z + bv.z);
            dst[3] = __float2half((x4.w - m)*rstd*gv.w + bv.w);
        }
    }

    const int rt2 = w8 >> 2;              // 32-row half (0..1)
    const int ct2 = w8 & 3;               // 32-col quarter (0..3)

    // ---- Phase 2: QKV via wmma, shared weight stage, half acc ----
    for (int c = 0; c < 3; ++c) {
        __syncthreads();
        for (int idx = tid; idx < 2048; idx += 512) {
            const int k = idx >> 4, u = idx & 15;
            *(uint4*)(Wc + k*AS + u*8) = *(const uint4*)(g_qkvwh + k*384 + c*128 + u*8);
        }
        __syncthreads();
        wmma::fragment<wmma::accumulator, 16, 16, 16, __half> c1[2][2];
        #pragma unroll
        for (int i = 0; i < 2; ++i)
            #pragma unroll
            for (int j = 0; j < 2; ++j) wmma::fill_fragment(c1[i][j], __float2half(0.f));
        #pragma unroll
        for (int ks = 0; ks < 8; ++ks) {
            wmma::fragment<wmma::matrix_a, 16, 16, 16, __half, wmma::row_major> fa[2];
            wmma::fragment<wmma::matrix_b, 16, 16, 16, __half, wmma::row_major> fb[2];
            #pragma unroll
            for (int i = 0; i < 2; ++i)
                wmma::load_matrix_sync(fa[i], Xh + (rt2*32 + i*16)*AS + ks*16, AS);
            #pragma unroll
            for (int j = 0; j < 2; ++j)
                wmma::load_matrix_sync(fb[j], Wc + ks*16*AS + ct2*32 + j*16, AS);
            #pragma unroll
            for (int i = 0; i < 2; ++i)
                #pragma unroll
                for (int j = 0; j < 2; ++j) wmma::mma_sync(c1[i][j], fa[i], fb[j], c1[i][j]);
        }
        __half* dest = (c == 0) ? Qh : (c == 1) ? Kh : Vh;
        #pragma unroll
        for (int i = 0; i < 2; ++i)
            #pragma unroll
            for (int j = 0; j < 2; ++j)
                wmma::store_matrix_sync(dest + (rt2*32 + i*16)*AS + ct2*32 + j*16, c1[i][j], AS, wmma::mem_row_major);
    }
    __syncthreads();        // Q/K/V visible; Wc reads done -> U reusable as Sh

    // ---- Phase 3: all-heads attention ----
    {
        const int h = w8 >> 1;
        const int p = w8 & 1;
        wmma::fragment<wmma::accumulator, 16, 16, 16, __half> sc[2][4];
        #pragma unroll
        for (int i = 0; i < 2; ++i)
            #pragma unroll
            for (int j = 0; j < 4; ++j) wmma::fill_fragment(sc[i][j], __float2half(0.f));
        #pragma unroll
        for (int ks = 0; ks < 2; ++ks) {
            wmma::fragment<wmma::matrix_a, 16, 16, 16, __half, wmma::row_major> fa[2];
            wmma::fragment<wmma::matrix_b, 16, 16, 16, __half, wmma::col_major> fb[4];
            #pragma unroll
            for (int i = 0; i < 2; ++i)
                wmma::load_matrix_sync(fa[i], Qh + (p*32 + i*16)*AS + h*32 + ks*16, AS);
            #pragma unroll
            for (int j = 0; j < 4; ++j)
                wmma::load_matrix_sync(fb[j], Kh + j*16*AS + h*32 + ks*16, AS);
            #pragma unroll
            for (int i = 0; i < 2; ++i)
                #pragma unroll
                for (int j = 0; j < 4; ++j) wmma::mma_sync(sc[i][j], fa[i], fb[j], sc[i][j]);
        }
        #pragma unroll
        for (int i = 0; i < 2; ++i)
            #pragma unroll
            for (int j = 0; j < 4; ++j)
                wmma::store_matrix_sync(Sh + h*HB + (p*32 + i*16)*SHS + j*16, sc[i][j], SHS, wmma::mem_row_major);
    }
    __syncthreads();

    // softmax: one thread per (win, head, row), fully in registers (half2)
    {
        const int shh = (tid >> 6) & 3;   // head
        const int si  = tid & 63;         // row
        __half* Srow = Sh + shh*HB + si*SHS;
        const int li = lab_s[si];
        const int lxi = si >> 4, lyi = (si >> 2) & 3, lzi = si & 3;
        half2 av[32];
        float mx = -1e30f;
        #pragma unroll
        for (int t = 0; t < 32; ++t) {
            const int j0 = 2*t;
            const float2 s2 = __half22float2(*(half2*)(Srow + j0));
            const int lxj = j0 >> 4, lyj = (j0 >> 2) & 3, lzj = j0 & 3;
            const int brow = 11*(lxi - lxj + 3) + (lyi - lyj + 3) + (lzi - lzj + 3);
            float a0 = s2.x + bias_s[brow*4 + shh];
            float a1 = s2.y + bias_s[(brow-1)*4 + shh];
            if (lab_s[j0]   != li) a0 -= 100.f;
            if (lab_s[j0+1] != li) a1 -= 100.f;
            mx = fmaxf(mx, fmaxf(a0, a1));
            av[t] = __floats2half2_rn(a0, a1);
        }
        const half2 mx2 = __float2half2_rn(mx);
        float sum = 0.f;
        #pragma unroll
        for (int t = 0; t < 32; ++t) {
            av[t] = h2exp(__hsub2(av[t], mx2));
            const float2 e2 = __half22float2(av[t]);
            sum += e2.x + e2.y;
        }
        const half2 inv2 = __float2half2_rn(1.f / sum);
        #pragma unroll
        for (int t = 0; t < 32; ++t)
            *(half2*)(Srow + 2*t) = __hmul2(av[t], inv2);
    }
    __syncthreads();

    // PV (all heads): half acc, store direct into Xh (O)
    {
        const int hh = w8 & 3;
        const int rp = w8 >> 2;
        wmma::fragment<wmma::accumulator, 16, 16, 16, __half> oc[2][2];
        #pragma unroll
        for (int i = 0; i < 2; ++i)
            #pragma unroll
            for (int j = 0; j < 2; ++j) wmma::fill_fragment(oc[i][j], __float2half(0.f));
        #pragma unroll
        for (int ks = 0; ks < 4; ++ks) {
            wmma::fragment<wmma::matrix_a, 16, 16, 16, __half, wmma::row_major> fa[2];
            wmma::fragment<wmma::matrix_b, 16, 16, 16, __half, wmma::row_major> fb[2];
            #pragma unroll
            for (int i = 0; i < 2; ++i)
                wmma::load_matrix_sync(fa[i], Sh + hh*HB + (rp*32 + i*16)*SHS + ks*16, SHS);
            #pragma unroll
            for (int j = 0; j < 2; ++j)
                wmma::load_matrix_sync(fb[j], Vh + ks*16*AS + hh*32 + j*16, AS);
            #pragma unroll
            for (int i = 0; i < 2; ++i)
                #pragma unroll
                for (int j = 0; j < 2; ++j) wmma::mma_sync(oc[i][j], fa[i], fb[j], oc[i][j]);
        }
        #pragma unroll
        for (int i = 0; i < 2; ++i)
            #pragma unroll
            for (int j = 0; j < 2; ++j)
                wmma::store_matrix_sync(Xh + (rp*32 + i*16)*AS + hh*32 + j*16, oc[i][j], AS, wmma::mem_row_major);
    }
    __syncthreads();        // Sh reads done -> U reusable as Wc; Xh (O) visible

    // ---- Phase 4: proj via wmma (half acc) -> Ph2 ----
    for (int idx = tid; idx < 2048; idx += 512) {
        const int k = idx >> 4, u = idx & 15;
        *(uint4*)(Wc + k*AS + u*8) = *(const uint4*)(g_projwh + k*128 + u*8);
    }
    __syncthreads();
    {
        wmma::fragment<wmma::accumulator, 16, 16, 16, __half> pc[2][2];
        #pragma unroll
        for (int i = 0; i < 2; ++i)
            #pragma unroll
            for (int j = 0; j < 2; ++j) wmma::fill_fragment(pc[i][j], __float2half(0.f));
        #pragma unroll
        for (int ks = 0; ks < 8; ++ks) {
            wmma::fragment<wmma::matrix_a, 16, 16, 16, __half, wmma::row_major> fa[2];
            wmma::fragment<wmma::matrix_b, 16, 16, 16, __half, wmma::row_major> fb[2];
            #pragma unroll
            for (int i = 0; i < 2; ++i)
                wmma::load_matrix_sync(fa[i], Xh + (rt2*32 + i*16)*AS + ks*16, AS);
            #pragma unroll
            for (int j = 0; j < 2; ++j)
                wmma::load_matrix_sync(fb[j], Wc + ks*16*AS + ct2*32 + j*16, AS);
            #pragma unroll
            for (int i = 0; i < 2; ++i)
                #pragma unroll
                for (int j = 0; j < 2; ++j) wmma::mma_sync(pc[i][j], fa[i], fb[j], pc[i][j]);
        }
        __syncthreads();    // Wc reads + Xh reads done -> U as Ph2
        #pragma unroll
        for (int i = 0; i < 2; ++i)
            #pragma unroll
            for (int j = 0; j < 2; ++j)
                wmma::store_matrix_sync(Ph2 + (rt2*32 + i*16)*HS2 + ct2*32 + j*16, pc[i][j], HS2, wmma::mem_row_major);
    }
    __syncthreads();

    // ---- Phase 5: residual rows -> smem Rf (f32) ----
    for (int idx = t256; idx < 2048; idx += 256) {
        const int r = idx >> 5, cg = idx & 31;
        const long base = (long)orow_s[r]*128;
        const half2 v01 = *(half2*)(Ph2 + r*HS2 + cg*4);
        const half2 v23 = *(half2*)(Ph2 + r*HS2 + cg*4 + 2);
        const float2 f01 = __half22float2(v01);
        const float2 f23 = __half22float2(v23);
        const float4 pb = *(const float4*)(proj_b + cg*4);
        const float4 xin = *(const float4*)(inp + base + cg*4);
        float4 o;
        o.x = 0.5f*(f01.x + pb.x) + xin.x;
        o.y = 0.5f*(f01.y + pb.y) + xin.y;
        o.z = 0.5f*(f23.x + pb.z) + xin.z;
        o.w = 0.5f*(f23.y + pb.w) + xin.w;
        *(float4*)(Rf + r*RFS + cg*4) = o;
    }
    __syncthreads();        // Rf visible; Ph2 reads done -> U free

    // ---- Phase 6: LN2 on Rf -> fp16 A1 (over Xh) ----
    {
        const float4 gv = *(const float4*)(g2 + lane*4);
        const float4 bv = *(const float4*)(b2 + lane*4);
        for (int t = w8*8; t < w8*8 + 8; ++t) {
            const float4 x4 = *(const float4*)(Rf + t*RFS + lane*4);
            float s = x4.x + x4.y + x4.z + x4.w;
            float q = x4.x*x4.x + x4.y*x4.y + x4.z*x4.z + x4.w*x4.w;
            #pragma unroll
            for (int o = 16; o; o >>= 1) {
                s += __shfl_xor_sync(0xffffffffu, s, o);
                q += __shfl_xor_sync(0xffffffffu, q, o);
            }
            const float m = s * 0.0078125f;
            const float rstd = rsqrtf(q*0.0078125f - m*m + 1e-5f);
            __half* dst = Xh + t*AS + lane*4;
            dst[0] = __float2half((x4.x - m)*rstd*gv.x + bv.x);
            dst[1] = __float2half((x4.y - m)*rstd*gv.y + bv.y);
            dst[2] = __float2half((x4.z - m)*rstd*gv.z + bv.z);
            dst[3] = __float2half((x4.w - m)*rstd*gv.w + bv.w);
        }
    }

    // ---- Phase 7: MLP, 4 chunks; A1=Xh, A2=Qh; shared weight stage ----
    wmma::fragment<wmma::accumulator, 16, 16, 16, float> acc2[2][2];
    #pragma unroll
    for (int i = 0; i < 2; ++i)
        #pragma unroll
        for (int j = 0; j < 2; ++j) wmma::fill_fragment(acc2[i][j], 0.f);

    for (int nb = 0; nb < 4; ++nb) {
        __syncthreads();    // A1 visible (nb=0) / prev gemm2 Wc reads done
        for (int idx = tid; idx < 2048; idx += 512) {
            const int k = idx >> 4, u = idx & 15;
            *(uint4*)(Wc + k*AS + u*8) = *(const uint4*)(g_w1h + k*512 + nb*128 + u*8);
        }
        __syncthreads();

        wmma::fragment<wmma::accumulator, 16, 16, 16, __half> c1[2][2];
        #pragma unroll
        for (int i = 0; i < 2; ++i)
            #pragma unroll
            for (int j = 0; j < 2; ++j) wmma::fill_fragment(c1[i][j], __float2half(0.f));
        #pragma unroll
        for (int ks = 0; ks < 8; ++ks) {
            wmma::fragment<wmma::matrix_a, 16, 16, 16, __half, wmma::row_major> fa[2];
            wmma::fragment<wmma::matrix_b, 16, 16, 16, __half, wmma::row_major> fb[2];
            #pragma unroll
            for (int i = 0; i < 2; ++i)
                wmma::load_matrix_sync(fa[i], Xh + (rt2*32 + i*16)*AS + ks*16, AS);
            #pragma unroll
            for (int j = 0; j < 2; ++j)
                wmma::load_matrix_sync(fb[j], Wc + ks*16*AS + ct2*32 + j*16, AS);
            #pragma unroll
            for (int i = 0; i < 2; ++i)
                #pragma unroll
                for (int j = 0; j < 2; ++j) wmma::mma_sync(c1[i][j], fa[i], fb[j], c1[i][j]);
        }
        __syncthreads();    // Wc reads done -> overlay Hs
        #pragma unroll
        for (int i = 0; i < 2; ++i)
            #pragma unroll
            for (int j = 0; j < 2; ++j)
                wmma::store_matrix_sync(Hs + (rt2*32 + i*16)*HS2 + ct2*32 + j*16, c1[i][j], HS2, wmma::mem_row_major);
        __syncthreads();

        // bias + exact GELU -> fp16 A2 (over Qh)
        for (int idx = t256; idx < 2048; idx += 256) {
            const int r = idx >> 5, cg = idx & 31;
            const half2 v01 = *(half2*)(Hs + r*HS2 + cg*4);
            const half2 v23 = *(half2*)(Hs + r*HS2 + cg*4 + 2);
            const float2 f01 = __half22float2(v01);
            const float2 f23 = __half22float2(v23);
            const float4 bv = *(const float4*)(bb1 + nb*128 + cg*4);
            float h0 = f01.x + bv.x, h1 = f01.y + bv.y, h2 = f23.x + bv.z, h3 = f23.y + bv.w;
            h0 = h0 * 0.5f * (1.f + erff(h0 * 0.70710678118654752f));
            h1 = h1 * 0.5f * (1.f + erff(h1 * 0.70710678118654752f));
            h2 = h2 * 0.5f * (1.f + erff(h2 * 0.70710678118654752f));
            h3 = h3 * 0.5f * (1.f + erff(h3 * 0.70710678118654752f));
            __half* dst = Qh + r*AS + cg*4;
            dst[0] = __float2half(h0); dst[1] = __float2half(h1);
            dst[2] = __float2half(h2); dst[3] = __float2half(h3);
        }
        __syncthreads();    // Hs reads done -> overlay Wc (w2 chunk)
        for (int idx = tid; idx < 2048; idx += 512) {
            const int k = idx >> 4, u = idx & 15;
            *(uint4*)(Wc + k*AS + u*8) = *(const uint4*)(g_w2h + (nb*128 + k)*128 + u*8);
        }
        __syncthreads();

        #pragma unroll
        for (int ks = 0; ks < 8; ++ks) {
            wmma::fragment<wmma::matrix_a, 16, 16, 16, __half, wmma::row_major> fa[2];
            wmma::fragment<wmma::matrix_b, 16, 16, 16, __half, wmma::row_major> fb[2];
            #pragma unroll
            for (int i = 0; i < 2; ++i)
                wmma::load_matrix_sync(fa[i], Qh + (rt2*32 + i*16)*AS + ks*16, AS);
            #pragma unroll
            for (int j = 0; j < 2; ++j)
                wmma::load_matrix_sync(fb[j], Wc + ks*16*AS + ct2*32 + j*16, AS);
            #pragma unroll
            for (int i = 0; i < 2; ++i)
                #pragma unroll
                for (int j = 0; j < 2; ++j) wmma::mma_sync(acc2[i][j], fa[i], fb[j], acc2[i][j]);
        }
    }

    __syncthreads();        // Wc reads done -> overlay Ff
    #pragma unroll
    for (int i = 0; i < 2; ++i)
        #pragma unroll
        for (int j = 0; j < 2; ++j)
            wmma::store_matrix_sync(Ff + (rt2*32 + i*16)*FS + ct2*32 + j*16, acc2[i][j], FS, wmma::mem_row_major);
    __syncthreads();

    // ---- Phase 8: final residual scatter to global ----
    for (int idx = t256; idx < 2048; idx += 256) {
        const int r = idx >> 5, cg = idx & 31;
        const long base = (long)orow_s[r]*128;
        const float4 v  = *(const float4*)(Ff + r*FS + cg*4);
        const float4 bv = *(const float4*)(bb2 + cg*4);
        const float4 rv = *(const float4*)(Rf + r*RFS + cg*4);
        float4 o;
        o.x = 0.5f*(v.x + bv.x) + rv.x;
        o.y = 0.5f*(v.y + bv.y) + rv.y;
        o.z = 0.5f*(v.z + bv.z) + rv.z;
        o.w = 0.5f*(v.w + bv.w) + rv.w;
        *(float4*)(out + base + cg*4) = o;
    }
}

// ---------------------------------------------------------------------------
extern "C" void kernel_launch(void* const* d_in, const int* in_sizes, int n_in,
                              void* d_out, int out_size) {
    const float* inputs     = (const float*)d_in[0];
    const float* qkv_w      = (const float*)d_in[1];
    const float* proj_w     = (const float*)d_in[2];
    const float* proj_b     = (const float*)d_in[3];
    const float* bias_table = (const float*)d_in[4];
    const float* g1         = (const float*)d_in[5];
    const float* b1         = (const float*)d_in[6];
    const float* g2         = (const float*)d_in[7];
    const float* b2         = (const float*)d_in[8];
    const float* w1         = (const float*)d_in[9];
    const float* bb1        = (const float*)d_in[10];
    const float* w2         = (const float*)d_in[11];
    const float* bb2        = (const float*)d_in[12];
    float* out = (float*)d_out;

    // tiles (2 windows) + U + bias + lab/orow
    const int smemA = 2*(4*64*AS)*2 + 73728 + 484*4 + 128*4 + 128*4;  // 215952 B

    cudaFuncSetAttribute(swin_block_kernel, cudaFuncAttributeMaxDynamicSharedMemorySize, smemA);

    cvt_weights_kernel<<<192, 256>>>(qkv_w, proj_w, w1, w2);
    swin_block_kernel<<<2048, 512, smemA>>>(inputs, proj_b, bias_table,
                                            g1, b1, g2, b2, bb1, bb2, out);
}

// round 16
// speedup vs baseline: 1.1266x; 1.1266x over previous
#include <cuda_runtime.h>
#include <cuda_fp16.h>
#include <mma.h>
#include <math.h>
#include <stdint.h>
#include <cstdint>

using namespace nvcuda;

#define AS 136    // fp16 tile stride (halfs, mult of 8)
#define FS 136    // f32 scratch stride (floats)
#define HS2 136   // half scratch stride (halfs)
#define SHS 72    // fp16 score row stride (halfs, mult of 8)
#define HB (64*SHS)  // per-head S block (halfs)
#define RFS 132   // residual f32 row stride (floats, mult of 4)
#define BTS 128   // bias tile stride (halfs, mult of 8)

// fp16 pre-converted weights (written by cvt_weights_kernel each launch)
// Q columns of qkv_w are pre-scaled by 1/sqrt(HD).
__device__ __align__(16) __half g_qkvwh[128*384];
__device__ __align__(16) __half g_projwh[128*128];
__device__ __align__(16) __half g_w1h[128*512];
__device__ __align__(16) __half g_w2h[512*128];

// ---------------------------------------------------------------------------
__global__ void cvt_weights_kernel(const float* __restrict__ qkv_w,
                                   const float* __restrict__ proj_w,
                                   const float* __restrict__ w1,
                                   const float* __restrict__ w2)
{
    const int i4 = (blockIdx.x*256 + threadIdx.x) * 4;   // grid 192 -> 196608
    const float* src; __half* dst; int off;
    float scale = 1.f;
    if (i4 < 49152) {
        src = qkv_w;  dst = g_qkvwh;  off = i4;
        if ((off % 384) < 128) scale = 0.17677669529663687f;   // fold qscale into Q
    }
    else if (i4 < 65536)  { src = proj_w; dst = g_projwh; off = i4 - 49152; }
    else if (i4 < 131072) { src = w1;     dst = g_w1h;    off = i4 - 65536; }
    else                  { src = w2;     dst = g_w2h;    off = i4 - 131072; }
    const float4 v = *(const float4*)(src + off);
    dst[off+0] = __float2half(v.x*scale); dst[off+1] = __float2half(v.y*scale);
    dst[off+2] = __float2half(v.z*scale); dst[off+3] = __float2half(v.w*scale);
}

__device__ __forceinline__ float gelu_f(float v) {
    return v * 0.5f * (1.f + erff(v * 0.70710678118654752f));
}

// ---------------------------------------------------------------------------
// Fused kernel (round-14 structure): LN1 -> QKV -> attention -> proj ->
// residual(smem) -> LN2 -> MLP (bias-in-fragment GELU, 4 barriers/chunk) ->
// scatter. One CTA per window, 256 threads, 2 CTA/SM.
// ---------------------------------------------------------------------------
__global__ void __launch_bounds__(256, 2) swin_block_kernel(
    const float* __restrict__ inp,
    const float* __restrict__ proj_b,
    const float* __restrict__ bias_table,
    const float* __restrict__ g1,
    const float* __restrict__ b1,
    const float* __restrict__ g2,
    const float* __restrict__ b2,
    const float* __restrict__ bb1,
    const float* __restrict__ bb2,
    float* __restrict__ out)
{
    extern __shared__ char sma[];
    __half* Xh = (__half*)sma;            // 64*AS (LN'd X; O; later MLP A1)
    __half* Qh = Xh + 64*AS;              // Q; later MLP A2
    __half* Kh = Qh + 64*AS;              // K; later Rf (f32 residual rows)
    __half* Vh = Kh + 64*AS;              // V; Rf tail
    char*   U  = (char*)(Vh + 64*AS);     // 36864B union: Wc / Sh / Ph2 / Ff
    __half* Wc  = (__half*)U;             // 128*AS halfs (34816B)
    __half* Sh  = (__half*)U;             // 4*HB halfs (36864B)
    __half* Ph2 = (__half*)U;             // 64*HS2 halfs proj scratch
    float*  Ff  = (float*)U;              // 64*FS floats gemm2 scratch
    float*  Rf  = (float*)Kh;             // 64*RFS floats residual (33792B)
    float*  bias_s = (float*)(U + 36864); // 484
    int*    lab_s  = (int*)(bias_s + 484);
    int*    orow_s = lab_s + 64;
    __half* BT = (__half*)(orow_s + 64);  // 16*BTS halfs bias tile (4096B)

    const int tid = threadIdx.x;
    const int warp = tid >> 5, lane = tid & 31;
    const int wblk = blockIdx.x;
    const int bb = wblk >> 9;
    const int wi = wblk & 511;
    const int gx = wi >> 6, gy = (wi >> 3) & 7, gz = wi & 7;

    for (int i = tid; i < 484; i += 256) bias_s[i] = bias_table[i];

    if (tid < 64) {
        const int lx = tid >> 4, ly = (tid >> 2) & 3, lz = tid & 3;
        const int px = gx*4 + lx, py = gy*4 + ly, pz = gz*4 + lz;
        const int ox = (px + 2) & 31, oy = (py + 2) & 31, oz = (pz + 2) & 31;
        orow_s[tid] = ((bb*32 + ox)*32 + oy)*32 + oz;
        const int labx = px < 28 ? 0 : (px < 30 ? 1 : 2);
        const int laby = py < 28 ? 0 : (py < 30 ? 1 : 2);
        const int labz = pz < 28 ? 0 : (pz < 30 ? 1 : 2);
        lab_s[tid] = labx*9 + laby*3 + labz;
    }
    __syncthreads();

    // ---- Phase 1: LayerNorm -> fp16 Xh ----
    {
        const float4 gv = *(const float4*)(g1 + lane*4);
        const float4 bv = *(const float4*)(b1 + lane*4);
        for (int t = warp*8; t < warp*8 + 8; ++t) {
            const float* row = inp + (long)orow_s[t]*128;
            const float4 x4 = *(const float4*)(row + lane*4);
            float s = x4.x + x4.y + x4.z + x4.w;
            float q = x4.x*x4.x + x4.y*x4.y + x4.z*x4.z + x4.w*x4.w;
            #pragma unroll
            for (int o = 16; o; o >>= 1) {
                s += __shfl_xor_sync(0xffffffffu, s, o);
                q += __shfl_xor_sync(0xffffffffu, q, o);
            }
            const float m = s * 0.0078125f;
            const float rstd = rsqrtf(q*0.0078125f - m*m + 1e-5f);
            __half* dst = Xh + t*AS + lane*4;
            dst[0] = __float2half((x4.x - m)*rstd*gv.x + bv.x);
            dst[1] = __float2half((x4.y - m)*rstd*gv.y + bv.y);
            dst[2] = __float2half((x4.z - m)*rstd*gv.z + bv.z);
            dst[3] = __float2half((x4.w - m)*rstd*gv.w + bv.w);
        }
    }

    const int rt2 = warp >> 2;            // 32-row half (0..1)
    const int ct2 = warp & 3;             // 32-col quarter (0..3)

    // ---- Phase 2: QKV via wmma, half accumulators, direct fp16 stores ----
    for (int c = 0; c < 3; ++c) {
        __syncthreads();
        for (int idx = tid; idx < 2048; idx += 256) {
            const int k = idx >> 4, u = idx & 15;
            *(uint4*)(Wc + k*AS + u*8) = *(const uint4*)(g_qkvwh + k*384 + c*128 + u*8);
        }
        __syncthreads();
        wmma::fragment<wmma::accumulator, 16, 16, 16, __half> c1[2][2];
        #pragma unroll
        for (int i = 0; i < 2; ++i)
            #pragma unroll
            for (int j = 0; j < 2; ++j) wmma::fill_fragment(c1[i][j], __float2half(0.f));
        #pragma unroll
        for (int ks = 0; ks < 8; ++ks) {
            wmma::fragment<wmma::matrix_a, 16, 16, 16, __half, wmma::row_major> fa[2];
            wmma::fragment<wmma::matrix_b, 16, 16, 16, __half, wmma::row_major> fb[2];
            #pragma unroll
            for (int i = 0; i < 2; ++i)
                wmma::load_matrix_sync(fa[i], Xh + (rt2*32 + i*16)*AS + ks*16, AS);
            #pragma unroll
            for (int j = 0; j < 2; ++j)
                wmma::load_matrix_sync(fb[j], Wc + ks*16*AS + ct2*32 + j*16, AS);
            #pragma unroll
            for (int i = 0; i < 2; ++i)
                #pragma unroll
                for (int j = 0; j < 2; ++j) wmma::mma_sync(c1[i][j], fa[i], fb[j], c1[i][j]);
        }
        __half* dest = (c == 0) ? Qh : (c == 1) ? Kh : Vh;
        #pragma unroll
        for (int i = 0; i < 2; ++i)
            #pragma unroll
            for (int j = 0; j < 2; ++j)
                wmma::store_matrix_sync(dest + (rt2*32 + i*16)*AS + ct2*32 + j*16, c1[i][j], AS, wmma::mem_row_major);
    }
    __syncthreads();        // Q/K/V visible; Wc reads done -> U reusable as Sh

    // ---- Phase 3: all-heads attention ----
    {
        const int h = warp >> 1;
        const int p = warp & 1;
        wmma::fragment<wmma::accumulator, 16, 16, 16, __half> sc[2][4];
        #pragma unroll
        for (int i = 0; i < 2; ++i)
            #pragma unroll
            for (int j = 0; j < 4; ++j) wmma::fill_fragment(sc[i][j], __float2half(0.f));
        #pragma unroll
        for (int ks = 0; ks < 2; ++ks) {
            wmma::fragment<wmma::matrix_a, 16, 16, 16, __half, wmma::row_major> fa[2];
            wmma::fragment<wmma::matrix_b, 16, 16, 16, __half, wmma::col_major> fb[4];
            #pragma unroll
            for (int i = 0; i < 2; ++i)
                wmma::load_matrix_sync(fa[i], Qh + (p*32 + i*16)*AS + h*32 + ks*16, AS);
            #pragma unroll
            for (int j = 0; j < 4; ++j)
                wmma::load_matrix_sync(fb[j], Kh + j*16*AS + h*32 + ks*16, AS);
            #pragma unroll
            for (int i = 0; i < 2; ++i)
                #pragma unroll
                for (int j = 0; j < 4; ++j) wmma::mma_sync(sc[i][j], fa[i], fb[j], sc[i][j]);
        }
        #pragma unroll
        for (int i = 0; i < 2; ++i)
            #pragma unroll
            for (int j = 0; j < 4; ++j)
                wmma::store_matrix_sync(Sh + h*HB + (p*32 + i*16)*SHS + j*16, sc[i][j], SHS, wmma::mem_row_major);
    }
    __syncthreads();

    // softmax: one thread per (head, row), fully in registers (half2)
    {
        const int shh = tid >> 6;
        const int si  = tid & 63;
        __half* Srow = Sh + shh*HB + si*SHS;
        const int li = lab_s[si];
        const int lxi = si >> 4, lyi = (si >> 2) & 3, lzi = si & 3;
        half2 av[32];
        float mx = -1e30f;
        #pragma unroll
        for (int t = 0; t < 32; ++t) {
            const int j0 = 2*t;
            const float2 s2 = __half22float2(*(half2*)(Srow + j0));
            const int lxj = j0 >> 4, lyj = (j0 >> 2) & 3, lzj = j0 & 3;
            const int brow = 11*(lxi - lxj + 3) + (lyi - lyj + 3) + (lzi - lzj + 3);
            float a0 = s2.x + bias_s[brow*4 + shh];
            float a1 = s2.y + bias_s[(brow-1)*4 + shh];
            if (lab_s[j0]   != li) a0 -= 100.f;
            if (lab_s[j0+1] != li) a1 -= 100.f;
            mx = fmaxf(mx, fmaxf(a0, a1));
            av[t] = __floats2half2_rn(a0, a1);
        }
        const half2 mx2 = __float2half2_rn(mx);
        float sum = 0.f;
        #pragma unroll
        for (int t = 0; t < 32; ++t) {
            av[t] = h2exp(__hsub2(av[t], mx2));
            const float2 e2 = __half22float2(av[t]);
            sum += e2.x + e2.y;
        }
        const half2 inv2 = __float2half2_rn(1.f / sum);
        #pragma unroll
        for (int t = 0; t < 32; ++t)
            *(half2*)(Srow + 2*t) = __hmul2(av[t], inv2);
    }
    __syncthreads();

    // PV (all heads): half acc, store direct into Xh (O)
    {
        const int hh = warp & 3;
        const int rp = warp >> 2;
        wmma::fragment<wmma::accumulator, 16, 16, 16, __half> oc[2][2];
        #pragma unroll
        for (int i = 0; i < 2; ++i)
            #pragma unroll
            for (int j = 0; j < 2; ++j) wmma::fill_fragment(oc[i][j], __float2half(0.f));
        #pragma unroll
        for (int ks = 0; ks < 4; ++ks) {
            wmma::fragment<wmma::matrix_a, 16, 16, 16, __half, wmma::row_major> fa[2];
            wmma::fragment<wmma::matrix_b, 16, 16, 16, __half, wmma::row_major> fb[2];
            #pragma unroll
            for (int i = 0; i < 2; ++i)
                wmma::load_matrix_sync(fa[i], Sh + hh*HB + (rp*32 + i*16)*SHS + ks*16, SHS);
            #pragma unroll
            for (int j = 0; j < 2; ++j)
                wmma::load_matrix_sync(fb[j], Vh + ks*16*AS + hh*32 + j*16, AS);
            #pragma unroll
            for (int i = 0; i < 2; ++i)
                #pragma unroll
                for (int j = 0; j < 2; ++j) wmma::mma_sync(oc[i][j], fa[i], fb[j], oc[i][j]);
        }
        #pragma unroll
        for (int i = 0; i < 2; ++i)
            #pragma unroll
            for (int j = 0; j < 2; ++j)
                wmma::store_matrix_sync(Xh + (rp*32 + i*16)*AS + hh*32 + j*16, oc[i][j], AS, wmma::mem_row_major);
    }
    __syncthreads();        // Sh reads done -> U reusable as Wc; Xh (O) visible

    // ---- Phase 4: proj via wmma (half acc) -> Ph2 ----
    for (int idx = tid; idx < 2048; idx += 256) {
        const int k = idx >> 4, u = idx & 15;
        *(uint4*)(Wc + k*AS + u*8) = *(const uint4*)(g_projwh + k*128 + u*8);
    }
    __syncthreads();
    {
        wmma::fragment<wmma::accumulator, 16, 16, 16, __half> pc[2][2];
        #pragma unroll
        for (int i = 0; i < 2; ++i)
            #pragma unroll
            for (int j = 0; j < 2; ++j) wmma::fill_fragment(pc[i][j], __float2half(0.f));
        #pragma unroll
        for (int ks = 0; ks < 8; ++ks) {
            wmma::fragment<wmma::matrix_a, 16, 16, 16, __half, wmma::row_major> fa[2];
            wmma::fragment<wmma::matrix_b, 16, 16, 16, __half, wmma::row_major> fb[2];
            #pragma unroll
            for (int i = 0; i < 2; ++i)
                wmma::load_matrix_sync(fa[i], Xh + (rt2*32 + i*16)*AS + ks*16, AS);
            #pragma unroll
            for (int j = 0; j < 2; ++j)
                wmma::load_matrix_sync(fb[j], Wc + ks*16*AS + ct2*32 + j*16, AS);
            #pragma unroll
            for (int i = 0; i < 2; ++i)
                #pragma unroll
                for (int j = 0; j < 2; ++j) wmma::mma_sync(pc[i][j], fa[i], fb[j], pc[i][j]);
        }
        __syncthreads();    // Wc reads + Xh reads done -> U as Ph2; Xh reusable
        #pragma unroll
        for (int i = 0; i < 2; ++i)
            #pragma unroll
            for (int j = 0; j < 2; ++j)
                wmma::store_matrix_sync(Ph2 + (rt2*32 + i*16)*HS2 + ct2*32 + j*16, pc[i][j], HS2, wmma::mem_row_major);
    }
    __syncthreads();

    // ---- Phase 5: residual rows -> smem Rf (f32), no global write ----
    for (int idx = tid; idx < 2048; idx += 256) {
        const int r = idx >> 5, cg = idx & 31;
        const long base = (long)orow_s[r]*128;
        const half2 v01 = *(half2*)(Ph2 + r*HS2 + cg*4);
        const half2 v23 = *(half2*)(Ph2 + r*HS2 + cg*4 + 2);
        const float2 f01 = __half22float2(v01);
        const float2 f23 = __half22float2(v23);
        const float4 pb = *(const float4*)(proj_b + cg*4);
        const float4 xin = *(const float4*)(inp + base + cg*4);
        float4 o;
        o.x = 0.5f*(f01.x + pb.x) + xin.x;
        o.y = 0.5f*(f01.y + pb.y) + xin.y;
        o.z = 0.5f*(f23.x + pb.z) + xin.z;
        o.w = 0.5f*(f23.y + pb.w) + xin.w;
        *(float4*)(Rf + r*RFS + cg*4) = o;
    }
    __syncthreads();        // Rf visible; Ph2 reads done -> U free

    // ---- Phase 6: LN2 on Rf -> fp16 A1 (over Xh) ----
    {
        const float4 gv = *(const float4*)(g2 + lane*4);
        const float4 bv = *(const float4*)(b2 + lane*4);
        for (int t = warp*8; t < warp*8 + 8; ++t) {
            const float4 x4 = *(const float4*)(Rf + t*RFS + lane*4);
            float s = x4.x + x4.y + x4.z + x4.w;
            float q = x4.x*x4.x + x4.y*x4.y + x4.z*x4.z + x4.w*x4.w;
            #pragma unroll
            for (int o = 16; o; o >>= 1) {
                s += __shfl_xor_sync(0xffffffffu, s, o);
                q += __shfl_xor_sync(0xffffffffu, q, o);
            }
            const float m = s * 0.0078125f;
            const float rstd = rsqrtf(q*0.0078125f - m*m + 1e-5f);
            __half* dst = Xh + t*AS + lane*4;
            dst[0] = __float2half((x4.x - m)*rstd*gv.x + bv.x);
            dst[1] = __float2half((x4.y - m)*rstd*gv.y + bv.y);
            dst[2] = __float2half((x4.z - m)*rstd*gv.z + bv.z);
            dst[3] = __float2half((x4.w - m)*rstd*gv.w + bv.w);
        }
    }

    // ---- Phase 7: MLP, 4 chunks; bias-in-fragment + in-register GELU ----
    wmma::fragment<wmma::accumulator, 16, 16, 16, float> acc2[2][2];
    #pragma unroll
    for (int i = 0; i < 2; ++i)
        #pragma unroll
        for (int j = 0; j < 2; ++j) wmma::fill_fragment(acc2[i][j], 0.f);

    for (int nb = 0; nb < 4; ++nb) {
        __syncthreads();    // A1 visible (nb=0) / prev gemm2 Wc+A2 reads done
        // stage w1 chunk + bb1 broadcast-rows bias tile
        for (int idx = tid; idx < 2048; idx += 256) {
            const int k = idx >> 4, u = idx & 15;
            *(uint4*)(Wc + k*AS + u*8) = *(const uint4*)(g_w1h + k*512 + nb*128 + u*8);
        }
        {
            // BT[r][c] = bb1[nb*128 + c] for r=0..15
            const int c8 = (tid & 15) * 8;        // col group
            const int rr = tid >> 4;              // row 0..15
            float4 b0 = *(const float4*)(bb1 + nb*128 + c8);
            float4 b1v = *(const float4*)(bb1 + nb*128 + c8 + 4);
            __half* dst = BT + rr*BTS + c8;
            dst[0] = __float2half(b0.x); dst[1] = __float2half(b0.y);
            dst[2] = __float2half(b0.z); dst[3] = __float2half(b0.w);
            dst[4] = __float2half(b1v.x); dst[5] = __float2half(b1v.y);
            dst[6] = __float2half(b1v.z); dst[7] = __float2half(b1v.w);
        }
        __syncthreads();

        // gemm1: c1 init from bias tile, MMA, in-register GELU, store -> A2(Qh)
        wmma::fragment<wmma::accumulator, 16, 16, 16, __half> c1[2][2];
        #pragma unroll
        for (int i = 0; i < 2; ++i)
            #pragma unroll
            for (int j = 0; j < 2; ++j)
                wmma::load_matrix_sync(c1[i][j], BT + ct2*32 + j*16, BTS, wmma::mem_row_major);
        #pragma unroll
        for (int ks = 0; ks < 8; ++ks) {
            wmma::fragment<wmma::matrix_a, 16, 16, 16, __half, wmma::row_major> fa[2];
            wmma::fragment<wmma::matrix_b, 16, 16, 16, __half, wmma::row_major> fb[2];
            #pragma unroll
            for (int i = 0; i < 2; ++i)
                wmma::load_matrix_sync(fa[i], Xh + (rt2*32 + i*16)*AS + ks*16, AS);
            #pragma unroll
            for (int j = 0; j < 2; ++j)
                wmma::load_matrix_sync(fb[j], Wc + ks*16*AS + ct2*32 + j*16, AS);
            #pragma unroll
            for (int i = 0; i < 2; ++i)
                #pragma unroll
                for (int j = 0; j < 2; ++j) wmma::mma_sync(c1[i][j], fa[i], fb[j], c1[i][j]);
        }
        #pragma unroll
        for (int i = 0; i < 2; ++i)
            #pragma unroll
            for (int j = 0; j < 2; ++j) {
                #pragma unroll
                for (int e = 0; e < c1[i][j].num_elements; ++e)
                    c1[i][j].x[e] = __float2half(gelu_f(__half2float(c1[i][j].x[e])));
                wmma::store_matrix_sync(Qh + (rt2*32 + i*16)*AS + ct2*32 + j*16, c1[i][j], AS, wmma::mem_row_major);
            }
        __syncthreads();    // Wc reads done -> stage w2
        for (int idx = tid; idx < 2048; idx += 256) {
            const int k = idx >> 4, u = idx & 15;
            *(uint4*)(Wc + k*AS + u*8) = *(const uint4*)(g_w2h + (nb*128 + k)*128 + u*8);
        }
        __syncthreads();    // w2 + all A2 tiles visible

        #pragma unroll
        for (int ks = 0; ks < 8; ++ks) {
            wmma::fragment<wmma::matrix_a, 16, 16, 16, __half, wmma::row_major> fa[2];
            wmma::fragment<wmma::matrix_b, 16, 16, 16, __half, wmma::row_major> fb[2];
            #pragma unroll
            for (int i = 0; i < 2; ++i)
                wmma::load_matrix_sync(fa[i], Qh + (rt2*32 + i*16)*AS + ks*16, AS);
            #pragma unroll
            for (int j = 0; j < 2; ++j)
                wmma::load_matrix_sync(fb[j], Wc + ks*16*AS + ct2*32 + j*16, AS);
            #pragma unroll
            for (int i = 0; i < 2; ++i)
                #pragma unroll
                for (int j = 0; j < 2; ++j) wmma::mma_sync(acc2[i][j], fa[i], fb[j], acc2[i][j]);
        }
    }

    __syncthreads();        // Wc reads done -> overlay Ff
    #pragma unroll
    for (int i = 0; i < 2; ++i)
        #pragma unroll
        for (int j = 0; j < 2; ++j)
            wmma::store_matrix_sync(Ff + (rt2*32 + i*16)*FS + ct2*32 + j*16, acc2[i][j], FS, wmma::mem_row_major);
    __syncthreads();

    // ---- Phase 8: final residual scatter to global ----
    for (int idx = tid; idx < 2048; idx += 256) {
        const int r = idx >> 5, cg = idx & 31;
        const long base = (long)orow_s[r]*128;
        const float4 v  = *(const float4*)(Ff + r*FS + cg*4);
        const float4 bv = *(const float4*)(bb2 + cg*4);
        const float4 rv = *(const float4*)(Rf + r*RFS + cg*4);
        float4 o;
        o.x = 0.5f*(v.x + bv.x) + rv.x;
        o.y = 0.5f*(v.y + bv.y) + rv.y;
        o.z = 0.5f*(v.z + bv.z) + rv.z;
        o.w = 0.5f*(v.w + bv.w) + rv.w;
        *(float4*)(out + base + cg*4) = o;
    }
}

// ---------------------------------------------------------------------------
extern "C" void kernel_launch(void* const* d_in, const int* in_sizes, int n_in,
                              void* d_out, int out_size) {
    const float* inputs     = (const float*)d_in[0];
    const float* qkv_w      = (const float*)d_in[1];
    const float* proj_w     = (const float*)d_in[2];
    const float* proj_b     = (const float*)d_in[3];
    const float* bias_table = (const float*)d_in[4];
    const float* g1         = (const float*)d_in[5];
    const float* b1         = (const float*)d_in[6];
    const float* g2         = (const float*)d_in[7];
    const float* b2         = (const float*)d_in[8];
    const float* w1         = (const float*)d_in[9];
    const float* bb1        = (const float*)d_in[10];
    const float* w2         = (const float*)d_in[11];
    const float* bb2        = (const float*)d_in[12];
    float* out = (float*)d_out;

    // tiles + U + bias + lab/orow + BT
    const int smemA = (4*64*AS)*2 + 36864 + 484*4 + 64*4 + 64*4 + 16*BTS*2;  // 113040 B

    cudaFuncSetAttribute(swin_block_kernel, cudaFuncAttributeMaxDynamicSharedMemorySize, smemA);

    cvt_weights_kernel<<<192, 256>>>(qkv_w, proj_w, w1, w2);
    swin_block_kernel<<<4096, 256, smemA>>>(inputs, proj_b, bias_table,
                                            g1, b1, g2, b2, bb1, bb2, out);
}

// round 17
// speedup vs baseline: 1.1719x; 1.0402x over previous
#include <cuda_runtime.h>
#include <cuda_fp16.h>
#include <mma.h>
#include <math.h>
#include <stdint.h>
#include <cstdint>

using namespace nvcuda;

#define AS 136    // fp16 tile stride (halfs, mult of 8)
#define FS 136    // f32 scratch stride (floats)
#define HS2 136   // half scratch stride (halfs)
#define SHS 72    // fp16 score row stride (halfs, mult of 8)
#define HB (64*SHS)  // per-head S block (halfs)
#define RFS 132   // residual f32 row stride (floats, mult of 4)

// fp16 pre-converted weights (written by cvt_weights_kernel each launch)
// Q columns of qkv_w are pre-scaled by 1/sqrt(HD).
__device__ __align__(16) __half g_qkvwh[128*384];
__device__ __align__(16) __half g_projwh[128*128];
__device__ __align__(16) __half g_w1h[128*512];
__device__ __align__(16) __half g_w2h[512*128];

// ---------------------------------------------------------------------------
__global__ void cvt_weights_kernel(const float* __restrict__ qkv_w,
                                   const float* __restrict__ proj_w,
                                   const float* __restrict__ w1,
                                   const float* __restrict__ w2)
{
    const int i4 = (blockIdx.x*256 + threadIdx.x) * 4;   // grid 192 -> 196608
    const float* src; __half* dst; int off;
    float scale = 1.f;
    if (i4 < 49152) {
        src = qkv_w;  dst = g_qkvwh;  off = i4;
        if ((off % 384) < 128) scale = 0.17677669529663687f;   // fold qscale into Q
    }
    else if (i4 < 65536)  { src = proj_w; dst = g_projwh; off = i4 - 49152; }
    else if (i4 < 131072) { src = w1;     dst = g_w1h;    off = i4 - 65536; }
    else                  { src = w2;     dst = g_w2h;    off = i4 - 131072; }
    const float4 v = *(const float4*)(src + off);
    dst[off+0] = __float2half(v.x*scale); dst[off+1] = __float2half(v.y*scale);
    dst[off+2] = __float2half(v.z*scale); dst[off+3] = __float2half(v.w*scale);
}

// ---------------------------------------------------------------------------
// Fused kernel (round-14 structure, minus two barriers):
// LN1 -> QKV -> attention -> proj(out->Qh) -> fused residual+LN2 ->
// MLP (4 chunks, Hs round-trip GELU) -> final scatter.
// One CTA per window, 256 threads, 2 CTA/SM.
// ---------------------------------------------------------------------------
__global__ void __launch_bounds__(256, 2) swin_block_kernel(
    const float* __restrict__ inp,
    const float* __restrict__ proj_b,
    const float* __restrict__ bias_table,
    const float* __restrict__ g1,
    const float* __restrict__ b1,
    const float* __restrict__ g2,
    const float* __restrict__ b2,
    const float* __restrict__ bb1,
    const float* __restrict__ bb2,
    float* __restrict__ out)
{
    extern __shared__ char sma[];
    __half* Xh = (__half*)sma;            // 64*AS (LN'd X; O; later MLP A1)
    __half* Qh = Xh + 64*AS;              // Q; proj output; later MLP A2
    __half* Kh = Qh + 64*AS;              // K; later Rf (f32 residual rows)
    __half* Vh = Kh + 64*AS;              // V; Rf tail
    char*   U  = (char*)(Vh + 64*AS);     // 36864B union: Wc / Sh / Hs / Ff
    __half* Wc  = (__half*)U;             // 128*AS halfs (34816B)
    __half* Sh  = (__half*)U;             // 4*HB halfs (36864B)
    __half* Hs  = (__half*)U;             // 64*HS2 halfs gemm1 scratch
    float*  Ff  = (float*)U;              // 64*FS floats gemm2 scratch
    float*  Rf  = (float*)Kh;             // 64*RFS floats residual (33792B)
    float*  bias_s = (float*)(U + 36864); // 484
    int*    lab_s  = (int*)(bias_s + 484);
    int*    orow_s = lab_s + 64;

    const int tid = threadIdx.x;
    const int warp = tid >> 5, lane = tid & 31;
    const int wblk = blockIdx.x;
    const int bb = wblk >> 9;
    const int wi = wblk & 511;
    const int gx = wi >> 6, gy = (wi >> 3) & 7, gz = wi & 7;

    for (int i = tid; i < 484; i += 256) bias_s[i] = bias_table[i];

    if (tid < 64) {
        const int lx = tid >> 4, ly = (tid >> 2) & 3, lz = tid & 3;
        const int px = gx*4 + lx, py = gy*4 + ly, pz = gz*4 + lz;
        const int ox = (px + 2) & 31, oy = (py + 2) & 31, oz = (pz + 2) & 31;
        orow_s[tid] = ((bb*32 + ox)*32 + oy)*32 + oz;
        const int labx = px < 28 ? 0 : (px < 30 ? 1 : 2);
        const int laby = py < 28 ? 0 : (py < 30 ? 1 : 2);
        const int labz = pz < 28 ? 0 : (pz < 30 ? 1 : 2);
        lab_s[tid] = labx*9 + laby*3 + labz;
    }
    __syncthreads();

    // ---- Phase 1: LayerNorm -> fp16 Xh ----
    {
        const float4 gv = *(const float4*)(g1 + lane*4);
        const float4 bv = *(const float4*)(b1 + lane*4);
        for (int t = warp*8; t < warp*8 + 8; ++t) {
            const float* row = inp + (long)orow_s[t]*128;
            const float4 x4 = *(const float4*)(row + lane*4);
            float s = x4.x + x4.y + x4.z + x4.w;
            float q = x4.x*x4.x + x4.y*x4.y + x4.z*x4.z + x4.w*x4.w;
            #pragma unroll
            for (int o = 16; o; o >>= 1) {
                s += __shfl_xor_sync(0xffffffffu, s, o);
                q += __shfl_xor_sync(0xffffffffu, q, o);
            }
            const float m = s * 0.0078125f;
            const float rstd = rsqrtf(q*0.0078125f - m*m + 1e-5f);
            __half* dst = Xh + t*AS + lane*4;
            dst[0] = __float2half((x4.x - m)*rstd*gv.x + bv.x);
            dst[1] = __float2half((x4.y - m)*rstd*gv.y + bv.y);
            dst[2] = __float2half((x4.z - m)*rstd*gv.z + bv.z);
            dst[3] = __float2half((x4.w - m)*rstd*gv.w + bv.w);
        }
    }

    const int rt2 = warp >> 2;            // 32-row half (0..1)
    const int ct2 = warp & 3;             // 32-col quarter (0..3)

    // ---- Phase 2: QKV via wmma, half accumulators, direct fp16 stores ----
    for (int c = 0; c < 3; ++c) {
        __syncthreads();
        for (int idx = tid; idx < 2048; idx += 256) {
            const int k = idx >> 4, u = idx & 15;
            *(uint4*)(Wc + k*AS + u*8) = *(const uint4*)(g_qkvwh + k*384 + c*128 + u*8);
        }
        __syncthreads();
        wmma::fragment<wmma::accumulator, 16, 16, 16, __half> c1[2][2];
        #pragma unroll
        for (int i = 0; i < 2; ++i)
            #pragma unroll
            for (int j = 0; j < 2; ++j) wmma::fill_fragment(c1[i][j], __float2half(0.f));
        #pragma unroll
        for (int ks = 0; ks < 8; ++ks) {
            wmma::fragment<wmma::matrix_a, 16, 16, 16, __half, wmma::row_major> fa[2];
            wmma::fragment<wmma::matrix_b, 16, 16, 16, __half, wmma::row_major> fb[2];
            #pragma unroll
            for (int i = 0; i < 2; ++i)
                wmma::load_matrix_sync(fa[i], Xh + (rt2*32 + i*16)*AS + ks*16, AS);
            #pragma unroll
            for (int j = 0; j < 2; ++j)
                wmma::load_matrix_sync(fb[j], Wc + ks*16*AS + ct2*32 + j*16, AS);
            #pragma unroll
            for (int i = 0; i < 2; ++i)
                #pragma unroll
                for (int j = 0; j < 2; ++j) wmma::mma_sync(c1[i][j], fa[i], fb[j], c1[i][j]);
        }
        __half* dest = (c == 0) ? Qh : (c == 1) ? Kh : Vh;
        #pragma unroll
        for (int i = 0; i < 2; ++i)
            #pragma unroll
            for (int j = 0; j < 2; ++j)
                wmma::store_matrix_sync(dest + (rt2*32 + i*16)*AS + ct2*32 + j*16, c1[i][j], AS, wmma::mem_row_major);
    }
    __syncthreads();        // Q/K/V visible; Wc reads done -> U reusable as Sh

    // ---- Phase 3: all-heads attention ----
    {
        const int h = warp >> 1;
        const int p = warp & 1;
        wmma::fragment<wmma::accumulator, 16, 16, 16, __half> sc[2][4];
        #pragma unroll
        for (int i = 0; i < 2; ++i)
            #pragma unroll
            for (int j = 0; j < 4; ++j) wmma::fill_fragment(sc[i][j], __float2half(0.f));
        #pragma unroll
        for (int ks = 0; ks < 2; ++ks) {
            wmma::fragment<wmma::matrix_a, 16, 16, 16, __half, wmma::row_major> fa[2];
            wmma::fragment<wmma::matrix_b, 16, 16, 16, __half, wmma::col_major> fb[4];
            #pragma unroll
            for (int i = 0; i < 2; ++i)
                wmma::load_matrix_sync(fa[i], Qh + (p*32 + i*16)*AS + h*32 + ks*16, AS);
            #pragma unroll
            for (int j = 0; j < 4; ++j)
                wmma::load_matrix_sync(fb[j], Kh + j*16*AS + h*32 + ks*16, AS);
            #pragma unroll
            for (int i = 0; i < 2; ++i)
                #pragma unroll
                for (int j = 0; j < 4; ++j) wmma::mma_sync(sc[i][j], fa[i], fb[j], sc[i][j]);
        }
        #pragma unroll
        for (int i = 0; i < 2; ++i)
            #pragma unroll
            for (int j = 0; j < 4; ++j)
                wmma::store_matrix_sync(Sh + h*HB + (p*32 + i*16)*SHS + j*16, sc[i][j], SHS, wmma::mem_row_major);
    }
    __syncthreads();

    // softmax: one thread per (head, row), fully in registers (half2)
    {
        const int shh = tid >> 6;
        const int si  = tid & 63;
        __half* Srow = Sh + shh*HB + si*SHS;
        const int li = lab_s[si];
        const int lxi = si >> 4, lyi = (si >> 2) & 3, lzi = si & 3;
        half2 av[32];
        float mx = -1e30f;
        #pragma unroll
        for (int t = 0; t < 32; ++t) {
            const int j0 = 2*t;
            const float2 s2 = __half22float2(*(half2*)(Srow + j0));
            const int lxj = j0 >> 4, lyj = (j0 >> 2) & 3, lzj = j0 & 3;
            const int brow = 11*(lxi - lxj + 3) + (lyi - lyj + 3) + (lzi - lzj + 3);
            float a0 = s2.x + bias_s[brow*4 + shh];
            float a1 = s2.y + bias_s[(brow-1)*4 + shh];
            if (lab_s[j0]   != li) a0 -= 100.f;
            if (lab_s[j0+1] != li) a1 -= 100.f;
            mx = fmaxf(mx, fmaxf(a0, a1));
            av[t] = __floats2half2_rn(a0, a1);
        }
        const half2 mx2 = __float2half2_rn(mx);
        float sum = 0.f;
        #pragma unroll
        for (int t = 0; t < 32; ++t) {
            av[t] = h2exp(__hsub2(av[t], mx2));
            const float2 e2 = __half22float2(av[t]);
            sum += e2.x + e2.y;
        }
        const half2 inv2 = __float2half2_rn(1.f / sum);
        #pragma unroll
        for (int t = 0; t < 32; ++t)
            *(half2*)(Srow + 2*t) = __hmul2(av[t], inv2);
    }
    __syncthreads();

    // PV (all heads): half acc, store direct into Xh (O)
    {
        const int hh = warp & 3;
        const int rp = warp >> 2;
        wmma::fragment<wmma::accumulator, 16, 16, 16, __half> oc[2][2];
        #pragma unroll
        for (int i = 0; i < 2; ++i)
            #pragma unroll
            for (int j = 0; j < 2; ++j) wmma::fill_fragment(oc[i][j], __float2half(0.f));
        #pragma unroll
        for (int ks = 0; ks < 4; ++ks) {
            wmma::fragment<wmma::matrix_a, 16, 16, 16, __half, wmma::row_major> fa[2];
            wmma::fragment<wmma::matrix_b, 16, 16, 16, __half, wmma::row_major> fb[2];
            #pragma unroll
            for (int i = 0; i < 2; ++i)
                wmma::load_matrix_sync(fa[i], Sh + hh*HB + (rp*32 + i*16)*SHS + ks*16, SHS);
            #pragma unroll
            for (int j = 0; j < 2; ++j)
                wmma::load_matrix_sync(fb[j], Vh + ks*16*AS + hh*32 + j*16, AS);
            #pragma unroll
            for (int i = 0; i < 2; ++i)
                #pragma unroll
                for (int j = 0; j < 2; ++j) wmma::mma_sync(oc[i][j], fa[i], fb[j], oc[i][j]);
        }
        #pragma unroll
        for (int i = 0; i < 2; ++i)
            #pragma unroll
            for (int j = 0; j < 2; ++j)
                wmma::store_matrix_sync(Xh + (rp*32 + i*16)*AS + hh*32 + j*16, oc[i][j], AS, wmma::mem_row_major);
    }
    __syncthreads();        // Sh reads done -> U reusable as Wc; Xh (O) visible

    // ---- Phase 4: proj via wmma (half acc), output direct into Qh ----
    // (Q is dead after the S-GEMM; each warp stores its own tiles.)
    for (int idx = tid; idx < 2048; idx += 256) {
        const int k = idx >> 4, u = idx & 15;
        *(uint4*)(Wc + k*AS + u*8) = *(const uint4*)(g_projwh + k*128 + u*8);
    }
    __syncthreads();
    {
        wmma::fragment<wmma::accumulator, 16, 16, 16, __half> pc[2][2];
        #pragma unroll
        for (int i = 0; i < 2; ++i)
            #pragma unroll
            for (int j = 0; j < 2; ++j) wmma::fill_fragment(pc[i][j], __float2half(0.f));
        #pragma unroll
        for (int ks = 0; ks < 8; ++ks) {
            wmma::fragment<wmma::matrix_a, 16, 16, 16, __half, wmma::row_major> fa[2];
            wmma::fragment<wmma::matrix_b, 16, 16, 16, __half, wmma::row_major> fb[2];
            #pragma unroll
            for (int i = 0; i < 2; ++i)
                wmma::load_matrix_sync(fa[i], Xh + (rt2*32 + i*16)*AS + ks*16, AS);
            #pragma unroll
            for (int j = 0; j < 2; ++j)
                wmma::load_matrix_sync(fb[j], Wc + ks*16*AS + ct2*32 + j*16, AS);
            #pragma unroll
            for (int i = 0; i < 2; ++i)
                #pragma unroll
                for (int j = 0; j < 2; ++j) wmma::mma_sync(pc[i][j], fa[i], fb[j], pc[i][j]);
        }
        #pragma unroll
        for (int i = 0; i < 2; ++i)
            #pragma unroll
            for (int j = 0; j < 2; ++j)
                wmma::store_matrix_sync(Qh + (rt2*32 + i*16)*AS + ct2*32 + j*16, pc[i][j], AS, wmma::mem_row_major);
    }
    __syncthreads();        // proj out (Qh) visible; Xh + Wc free

    // ---- Phase 5+6 fused: residual -> Rf AND LN2 -> fp16 A1 (over Xh) ----
    // Same thread layout as LN: warp = rows warp*8..+7, lane = cols lane*4..+3.
    {
        const float4 pb  = *(const float4*)(proj_b + lane*4);
        const float4 gv = *(const float4*)(g2 + lane*4);
        const float4 bv = *(const float4*)(b2 + lane*4);
        for (int t = warp*8; t < warp*8 + 8; ++t) {
            const half2 v01 = *(half2*)(Qh + t*AS + lane*4);
            const half2 v23 = *(half2*)(Qh + t*AS + lane*4 + 2);
            const float2 f01 = __half22float2(v01);
            const float2 f23 = __half22float2(v23);
            const float4 xin = *(const float4*)(inp + (long)orow_s[t]*128 + lane*4);
            float4 r;
            r.x = 0.5f*(f01.x + pb.x) + xin.x;
            r.y = 0.5f*(f01.y + pb.y) + xin.y;
            r.z = 0.5f*(f23.x + pb.z) + xin.z;
            r.w = 0.5f*(f23.y + pb.w) + xin.w;
            *(float4*)(Rf + t*RFS + lane*4) = r;
            float s = r.x + r.y + r.z + r.w;
            float q = r.x*r.x + r.y*r.y + r.z*r.z + r.w*r.w;
            #pragma unroll
            for (int o = 16; o; o >>= 1) {
                s += __shfl_xor_sync(0xffffffffu, s, o);
                q += __shfl_xor_sync(0xffffffffu, q, o);
            }
            const float m = s * 0.0078125f;
            const float rstd = rsqrtf(q*0.0078125f - m*m + 1e-5f);
            __half* dst = Xh + t*AS + lane*4;
            dst[0] = __float2half((r.x - m)*rstd*gv.x + bv.x);
            dst[1] = __float2half((r.y - m)*rstd*gv.y + bv.y);
            dst[2] = __float2half((r.z - m)*rstd*gv.z + bv.z);
            dst[3] = __float2half((r.w - m)*rstd*gv.w + bv.w);
        }
    }

    // ---- Phase 7: MLP, 4 chunks; A1=Xh, A2=Qh, scratch in U ----
    wmma::fragment<wmma::accumulator, 16, 16, 16, float> acc2[2][2];
    #pragma unroll
    for (int i = 0; i < 2; ++i)
        #pragma unroll
        for (int j = 0; j < 2; ++j) wmma::fill_fragment(acc2[i][j], 0.f);

    for (int nb = 0; nb < 4; ++nb) {
        __syncthreads();    // A1/Rf visible (nb=0) / prev gemm2 Wc reads done
        for (int idx = tid; idx < 2048; idx += 256) {
            const int k = idx >> 4, u = idx & 15;
            *(uint4*)(Wc + k*AS + u*8) = *(const uint4*)(g_w1h + k*512 + nb*128 + u*8);
        }
        __syncthreads();

        wmma::fragment<wmma::accumulator, 16, 16, 16, __half> c1[2][2];
        #pragma unroll
        for (int i = 0; i < 2; ++i)
            #pragma unroll
            for (int j = 0; j < 2; ++j) wmma::fill_fragment(c1[i][j], __float2half(0.f));
        #pragma unroll
        for (int ks = 0; ks < 8; ++ks) {
            wmma::fragment<wmma::matrix_a, 16, 16, 16, __half, wmma::row_major> fa[2];
            wmma::fragment<wmma::matrix_b, 16, 16, 16, __half, wmma::row_major> fb[2];
            #pragma unroll
            for (int i = 0; i < 2; ++i)
                wmma::load_matrix_sync(fa[i], Xh + (rt2*32 + i*16)*AS + ks*16, AS);
            #pragma unroll
            for (int j = 0; j < 2; ++j)
                wmma::load_matrix_sync(fb[j], Wc + ks*16*AS + ct2*32 + j*16, AS);
            #pragma unroll
            for (int i = 0; i < 2; ++i)
                #pragma unroll
                for (int j = 0; j < 2; ++j) wmma::mma_sync(c1[i][j], fa[i], fb[j], c1[i][j]);
        }
        __syncthreads();    // Wc reads done -> overlay Hs
        #pragma unroll
        for (int i = 0; i < 2; ++i)
            #pragma unroll
            for (int j = 0; j < 2; ++j)
                wmma::store_matrix_sync(Hs + (rt2*32 + i*16)*HS2 + ct2*32 + j*16, c1[i][j], HS2, wmma::mem_row_major);
        __syncthreads();

        // bias + exact GELU -> fp16 A2 (over Qh)
        for (int idx = tid; idx < 2048; idx += 256) {
            const int r = idx >> 5, cg = idx & 31;
            const half2 v01 = *(half2*)(Hs + r*HS2 + cg*4);
            const half2 v23 = *(half2*)(Hs + r*HS2 + cg*4 + 2);
            const float2 f01 = __half22float2(v01);
            const float2 f23 = __half22float2(v23);
            const float4 bv = *(const float4*)(bb1 + nb*128 + cg*4);
            float h0 = f01.x + bv.x, h1 = f01.y + bv.y, h2 = f23.x + bv.z, h3 = f23.y + bv.w;
            h0 = h0 * 0.5f * (1.f + erff(h0 * 0.70710678118654752f));
            h1 = h1 * 0.5f * (1.f + erff(h1 * 0.70710678118654752f));
            h2 = h2 * 0.5f * (1.f + erff(h2 * 0.70710678118654752f));
            h3 = h3 * 0.5f * (1.f + erff(h3 * 0.70710678118654752f));
            __half* dst = Qh + r*AS + cg*4;
            dst[0] = __float2half(h0); dst[1] = __float2half(h1);
            dst[2] = __float2half(h2); dst[3] = __float2half(h3);
        }
        __syncthreads();    // Hs reads done -> overlay Wc (w2 chunk)
        for (int idx = tid; idx < 2048; idx += 256) {
            const int k = idx >> 4, u = idx & 15;
            *(uint4*)(Wc + k*AS + u*8) = *(const uint4*)(g_w2h + (nb*128 + k)*128 + u*8);
        }
        __syncthreads();

        #pragma unroll
        for (int ks = 0; ks < 8; ++ks) {
            wmma::fragment<wmma::matrix_a, 16, 16, 16, __half, wmma::row_major> fa[2];
            wmma::fragment<wmma::matrix_b, 16, 16, 16, __half, wmma::row_major> fb[2];
            #pragma unroll
            for (int i = 0; i < 2; ++i)
                wmma::load_matrix_sync(fa[i], Qh + (rt2*32 + i*16)*AS + ks*16, AS);
            #pragma unroll
            for (int j = 0; j < 2; ++j)
                wmma::load_matrix_sync(fb[j], Wc + ks*16*AS + ct2*32 + j*16, AS);
            #pragma unroll
            for (int i = 0; i < 2; ++i)
                #pragma unroll
                for (int j = 0; j < 2; ++j) wmma::mma_sync(acc2[i][j], fa[i], fb[j], acc2[i][j]);
        }
    }

    __syncthreads();        // Wc reads done -> overlay Ff
    #pragma unroll
    for (int i = 0; i < 2; ++i)
        #pragma unroll
        for (int j = 0; j < 2; ++j)
            wmma::store_matrix_sync(Ff + (rt2*32 + i*16)*FS + ct2*32 + j*16, acc2[i][j], FS, wmma::mem_row_major);
    __syncthreads();

    // ---- Phase 8: final residual scatter to global ----
    for (int idx = tid; idx < 2048; idx += 256) {
        const int r = idx >> 5, cg = idx & 31;
        const long base = (long)orow_s[r]*128;
        const float4 v  = *(const float4*)(Ff + r*FS + cg*4);
        const float4 bv = *(const float4*)(bb2 + cg*4);
        const float4 rv = *(const float4*)(Rf + r*RFS + cg*4);
        float4 o;
        o.x = 0.5f*(v.x + bv.x) + rv.x;
        o.y = 0.5f*(v.y + bv.y) + rv.y;
        o.z = 0.5f*(v.z + bv.z) + rv.z;
        o.w = 0.5f*(v.w + bv.w) + rv.w;
        *(float4*)(out + base + cg*4) = o;
    }
}

// ---------------------------------------------------------------------------
extern "C" void kernel_launch(void* const* d_in, const int* in_sizes, int n_in,
                              void* d_out, int out_size) {
    const float* inputs     = (const float*)d_in[0];
    const float* qkv_w      = (const float*)d_in[1];
    const float* proj_w     = (const float*)d_in[2];
    const float* proj_b     = (const float*)d_in[3];
    const float* bias_table = (const float*)d_in[4];
    const float* g1         = (const float*)d_in[5];
    const float* b1         = (const float*)d_in[6];
    const float* g2         = (const float*)d_in[7];
    const float* b2         = (const float*)d_in[8];
    const float* w1         = (const float*)d_in[9];
    const float* bb1        = (const float*)d_in[10];
    const float* w2         = (const float*)d_in[11];
    const float* bb2        = (const float*)d_in[12];
    float* out = (float*)d_out;

    const int smemA = (4*64*AS)*2 + 36864 + 484*4 + 64*4 + 64*4;   // 108944 B

    cudaFuncSetAttribute(swin_block_kernel, cudaFuncAttributeMaxDynamicSharedMemorySize, smemA);

    cvt_weights_kernel<<<192, 256>>>(qkv_w, proj_w, w1, w2);
    swin_block_kernel<<<4096, 256, smemA>>>(inputs, proj_b, bias_table,
                                            g1, b1, g2, b2, bb1, bb2, out);
}